// round 7
// baseline (speedup 1.0000x reference)
#include <cuda_runtime.h>
#include <cstdint>
#include <cstddef>

#define BB 256
#define TT 512
#define NN 128
#define GO_IDX 1
#define EOS_IDX 2
#define NEGV -10000.0f
#define FULLM 0xffffffffu
#define GPAD 20   // padded stride (floats) per 16-float prev-group: conflict-free

__device__ float g_alpha[(size_t)BB * TT * NN];   // alpha_t rows
__device__ float g_mval [(size_t)BB * TT * NN];   // pre-unary max rows
__device__ float g_m [BB * TT];
__device__ float g_ls[BB * TT];
__device__ float g_score[BB];
__device__ int   g_bestTag[BB];

__device__ __forceinline__ int load_len(const void* lp, int b) {
    const int* p32 = (const int*)lp;
    if (p32[1] == 0) return (int)((const long long*)lp)[b];
    return p32[b];
}

// packed f32x2 add: two independent rn adds, bitwise == scalar FADD
__device__ __forceinline__ float2 add2(float2 a, float2 b) {
    double r;
    asm("add.rn.f32x2 %0, %1, %2;"
        : "=d"(r)
        : "d"(*reinterpret_cast<double*>(&a)), "d"(*reinterpret_cast<double*>(&b)));
    return *reinterpret_cast<float2*>(&r);
}

// FFMA-pipe exp (~1e-9 rel on [-87,0])
__device__ __forceinline__ float fexp(float x) {
    float t  = fmaf(x, 1.4426950408889634f, 12582912.0f);
    int   ni = __float_as_int(t) - 0x4B400000;
    float n  = t - 12582912.0f;
    float r  = fmaf(n, -0.693359375f, x);
    r        = fmaf(n,  2.12194440e-4f, r);
    float p  = 1.9841270e-4f;
    p = fmaf(p, r, 1.3888889e-3f);
    p = fmaf(p, r, 8.3333333e-3f);
    p = fmaf(p, r, 4.1666667e-2f);
    p = fmaf(p, r, 1.6666667e-1f);
    p = fmaf(p, r, 0.5f);
    p = fmaf(p, r, 1.0f);
    p = fmaf(p, r, 1.0f);
    int e = ni + 127; if (e < 1) e = 1;
    return p * __int_as_float(e << 23);
}

// ---------------------------------------------------------------------------
// Kernel 1: per-(b,t) log-softmax stats, 1 warp/row.
// ---------------------------------------------------------------------------
__global__ __launch_bounds__(256)
void lse_kernel(const float* __restrict__ unaries)
{
    const int row  = blockIdx.x * 8 + (threadIdx.x >> 5);
    const int lane = threadIdx.x & 31;
    float4 uv = ((const float4*)(unaries + (size_t)row * NN))[lane];
    float m = fmaxf(fmaxf(uv.x, uv.y), fmaxf(uv.z, uv.w));
    #pragma unroll
    for (int off = 16; off; off >>= 1)
        m = fmaxf(m, __shfl_xor_sync(FULLM, m, off));
    float s = fexp(uv.x - m) + fexp(uv.y - m) + fexp(uv.z - m) + fexp(uv.w - m);
    #pragma unroll
    for (int off = 16; off; off >>= 1)
        s += __shfl_xor_sync(FULLM, s, off);
    if (lane == 0) { g_m[row] = m; g_ls[row] = logf(s); }
}

// ---------------------------------------------------------------------------
// Kernel 2: forward, pure max. 1024 threads/CTA, tid = cur*8 + g.
// Each thread: 16 trans values in regs (float2[8]), 16 prev tags.
// Alphas double-buffered in padded smem; one barrier/step; u/m/ls prefetched
// one step ahead. Spill-free (~45 regs).
// ---------------------------------------------------------------------------
__global__ __launch_bounds__(1024, 1)
void viterbi_forward(const float* __restrict__ unaries,
                     const float* __restrict__ trans,
                     const void*  __restrict__ lengths)
{
    __shared__ float abuf[2][8 * GPAD];

    const int b   = blockIdx.x;
    const int tid = threadIdx.x;
    const int cur = tid >> 3;
    const int g   = tid & 7;     // prev-group: prev in [g*16, g*16+16)
    const int L   = load_len(lengths, b);

    // loop-invariant transition scores (16 floats = 8 packed pairs)
    float2 tr[8];
    #pragma unroll
    for (int j = 0; j < 8; ++j)
        tr[j] = *(const float2*)(trans + cur * NN + g * 16 + j * 2);

    if (g == 0) {
        int p = cur;
        abuf[0][(p >> 4) * GPAD + (p & 15)] = (p == GO_IDX) ? 0.0f : NEGV;
    }

    const float* urow = unaries + (size_t)b * TT * NN;
    const float* gmp  = g_m  + b * TT;
    const float* glp  = g_ls + b * TT;
    float* aout = g_alpha + (size_t)b * TT * NN;
    float* mout = g_mval  + (size_t)b * TT * NN;

    // prefetch step-0 stats
    float u = 0.f, mm = 0.f, lls = 0.f;
    if (g == 0) {
        u   = __ldg(urow + cur);
        mm  = __ldg(gmp);
        lls = __ldg(glp);
    }
    __syncthreads();

    for (int t = 0; t < L; ++t) {
        // issue next-step loads early (fully hides L2 latency)
        float u2 = 0.f, mm2 = 0.f, lls2 = 0.f;
        if (g == 0) {
            int tn = (t + 1 < L) ? t + 1 : t;
            u2   = __ldg(urow + (size_t)tn * NN + cur);
            mm2  = __ldg(gmp + tn);
            lls2 = __ldg(glp + tn);
        }

        const float* aS = abuf[t & 1] + g * GPAD;  // bank-disjoint per g

        float2 s0 = add2(*(const float2*)(aS + 0),  tr[0]);
        float2 s1 = add2(*(const float2*)(aS + 2),  tr[1]);
        float2 s2 = add2(*(const float2*)(aS + 4),  tr[2]);
        float2 s3 = add2(*(const float2*)(aS + 6),  tr[3]);
        float2 s4 = add2(*(const float2*)(aS + 8),  tr[4]);
        float2 s5 = add2(*(const float2*)(aS + 10), tr[5]);
        float2 s6 = add2(*(const float2*)(aS + 12), tr[6]);
        float2 s7 = add2(*(const float2*)(aS + 14), tr[7]);

        float a0 = fmaxf(fmaxf(s0.x, s0.y), fmaxf(s1.x, s1.y));
        float a1 = fmaxf(fmaxf(s2.x, s2.y), fmaxf(s3.x, s3.y));
        float a2 = fmaxf(fmaxf(s4.x, s4.y), fmaxf(s5.x, s5.y));
        float a3 = fmaxf(fmaxf(s6.x, s6.y), fmaxf(s7.x, s7.y));
        float bv = fmaxf(fmaxf(a0, a1), fmaxf(a2, a3));

        // combine the 8 prev-groups (adjacent lanes)
        bv = fmaxf(bv, __shfl_xor_sync(FULLM, bv, 1));
        bv = fmaxf(bv, __shfl_xor_sync(FULLM, bv, 2));
        bv = fmaxf(bv, __shfl_xor_sync(FULLM, bv, 4));

        if (g == 0) {
            float a = bv + ((u - mm) - lls);           // exact passing formula
            abuf[(t + 1) & 1][(cur >> 4) * GPAD + (cur & 15)] = a;
            aout[(size_t)t * NN + cur] = a;
            mout[(size_t)t * NN + cur] = bv;
        }
        u = u2; mm = mm2; lls = lls2;
        __syncthreads();
    }

    // terminal argmax over prev (first-index), warp 0 only
    if (tid < 32) {
        const float* aF = abuf[L & 1];
        float bv = __int_as_float(0xff800000); int bi = 0;
        #pragma unroll
        for (int k = 0; k < 4; ++k) {
            int c = tid * 4 + k;
            float v = aF[(c >> 4) * GPAD + (c & 15)] + __ldg(trans + EOS_IDX * NN + c);
            if (v > bv) { bv = v; bi = c; }            // in-order: first-index ties
        }
        #pragma unroll
        for (int off = 16; off; off >>= 1) {
            float ov = __shfl_xor_sync(FULLM, bv, off);
            int   oi = __shfl_xor_sync(FULLM, bi, off);
            if (ov > bv || (ov == bv && oi < bi)) { bv = ov; bi = oi; }
        }
        if (tid == 0) { g_score[b] = bv; g_bestTag[b] = bi; }
    }
}

// ---------------------------------------------------------------------------
// Kernel 3: backtrace via equality against stored m (proven in R3-R5).
// ---------------------------------------------------------------------------
#define BT_SMEM (65536 + 8 * TT * 4)

__global__ __launch_bounds__(256)
void viterbi_backtrace(const float* __restrict__ trans,
                       const void*  __restrict__ lengths,
                       void* __restrict__ outv, int mode)
{
    extern __shared__ char smem[];
    float4* trS  = (float4*)smem;                 // [128][32] float4
    int*    path = (int*)(smem + 65536);          // [8][TT]

    const int tid = threadIdx.x;
    for (int i = tid; i < 128 * 32; i += 256)
        trS[i] = ((const float4*)trans)[i];
    __syncthreads();

    const int w    = tid >> 5;
    const int lane = tid & 31;
    const int b    = blockIdx.x * 8 + w;
    const int L    = load_len(lengths, b);
    int cur = g_bestTag[b];
    int* mypath = path + w * TT;
    if (lane == 0) mypath[L - 1] = cur;

    const float4* arow = (const float4*)(g_alpha + (size_t)b * TT * NN);
    const float4* mrow = (const float4*)(g_mval  + (size_t)b * TT * NN);

    const int t0 = L - 1;
    float4 ab0, ab1, mb0, mb1;
    ab0 = ab1 = mb0 = mb1 = make_float4(0.f, 0.f, 0.f, 0.f);
    if (t0 >= 1) { ab0 = arow[(size_t)(t0 - 1) * 32 + lane]; mb0 = mrow[(size_t)t0 * 32 + lane]; }
    if (t0 >= 2) { ab1 = arow[(size_t)(t0 - 2) * 32 + lane]; mb1 = mrow[(size_t)(t0 - 1) * 32 + lane]; }

    for (int t = t0; t >= 1; --t) {
        const int par = (t0 - t) & 1;
        float4 av = par ? ab1 : ab0;
        float4 mv = par ? mb1 : mb0;
        if (t >= 3) {
            float4 na = arow[(size_t)(t - 3) * 32 + lane];
            float4 nm = mrow[(size_t)(t - 2) * 32 + lane];
            if (par) { ab1 = na; mb1 = nm; } else { ab0 = na; mb0 = nm; }
        }
        const int sl   = cur >> 2;
        const int comp = cur & 3;
        float mc = (comp == 0) ? mv.x : (comp == 1) ? mv.y : (comp == 2) ? mv.z : mv.w;
        float mstar = __shfl_sync(FULLM, mc, sl);

        float4 tv = trS[cur * 32 + lane];
        float v0 = av.x + tv.x, v1 = av.y + tv.y;
        float v2 = av.z + tv.z, v3 = av.w + tv.w;
        bool e0 = (v0 == mstar), e1 = (v1 == mstar);
        bool e2 = (v2 == mstar), e3 = (v3 == mstar);
        unsigned mask = __ballot_sync(FULLM, e0 | e1 | e2 | e3);
        int wl = __ffs(mask) - 1;
        int lj = 3; if (e2) lj = 2; if (e1) lj = 1; if (e0) lj = 0;
        int ljw = __shfl_sync(FULLM, lj, wl);
        cur = wl * 4 + ljw;
        if (lane == 0) mypath[t - 1] = cur;
    }
    __syncwarp();

    float* outf = (float*)outv;
    int*   outi = (int*)outv;
    for (int tt = lane; tt < TT; tt += 32) {
        int v = (tt < L) ? mypath[tt] : 0;
        if (mode) outf[b * TT + tt] = (float)v;
        else      outi[b * TT + tt] = v;
    }
    if (mode && lane == 0) outf[BB * TT + b] = g_score[b];
}

extern "C" void kernel_launch(void* const* d_in, const int* in_sizes, int n_in,
                              void* d_out, int out_size)
{
    const float* unaries = (const float*)d_in[0];
    const float* trans   = (const float*)d_in[1];
    const void*  lengths = d_in[2];

    cudaFuncSetAttribute(viterbi_backtrace,
                         cudaFuncAttributeMaxDynamicSharedMemorySize, BT_SMEM);

    const int mode = (out_size == BB * TT + BB) ? 1 : 0;

    lse_kernel<<<(BB * TT) / 8, 256>>>(unaries);
    viterbi_forward<<<BB, 1024>>>(unaries, trans, lengths);
    viterbi_backtrace<<<32, 256, BT_SMEM>>>(trans, lengths, d_out, mode);
}

// round 9
// speedup vs baseline: 1.0062x; 1.0062x over previous
#include <cuda_runtime.h>
#include <cstdint>
#include <cstddef>

#define BB 256
#define TT 512
#define NN 128
#define GO_IDX 1
#define EOS_IDX 2
#define NEGV -10000.0f
#define FULLM 0xffffffffu
#define GP 36   // padded stride (floats) per 32-float prev-group (144B, 16B-aligned)

__device__ float g_alpha[(size_t)BB * TT * NN];   // alpha_t rows
__device__ float g_mval [(size_t)BB * TT * NN];   // pre-unary max rows
__device__ float g_p    [(size_t)BB * TT * NN];   // precomputed log_softmax(unaries)
__device__ float g_score[BB];
__device__ int   g_bestTag[BB];

__device__ __forceinline__ int load_len(const void* lp, int b) {
    const int* p32 = (const int*)lp;
    if (p32[1] == 0) return (int)((const long long*)lp)[b];
    return p32[b];
}

// packed f32x2 add: two independent rn adds, bitwise == scalar FADD
__device__ __forceinline__ float2 add2(float2 a, float2 b) {
    double r;
    asm("add.rn.f32x2 %0, %1, %2;"
        : "=d"(r)
        : "d"(*reinterpret_cast<double*>(&a)), "d"(*reinterpret_cast<double*>(&b)));
    return *reinterpret_cast<float2*>(&r);
}

// FFMA-pipe exp (~1e-9 rel on [-87,0])
__device__ __forceinline__ float fexp(float x) {
    float t  = fmaf(x, 1.4426950408889634f, 12582912.0f);
    int   ni = __float_as_int(t) - 0x4B400000;
    float n  = t - 12582912.0f;
    float r  = fmaf(n, -0.693359375f, x);
    r        = fmaf(n,  2.12194440e-4f, r);
    float p  = 1.9841270e-4f;
    p = fmaf(p, r, 1.3888889e-3f);
    p = fmaf(p, r, 8.3333333e-3f);
    p = fmaf(p, r, 4.1666667e-2f);
    p = fmaf(p, r, 1.6666667e-1f);
    p = fmaf(p, r, 0.5f);
    p = fmaf(p, r, 1.0f);
    p = fmaf(p, r, 1.0f);
    int e = ni + 127; if (e < 1) e = 1;
    return p * __int_as_float(e << 23);
}

// ---------------------------------------------------------------------------
// Kernel 1: per-(b,t) log-softmax, fully materialized: p = (u - m) - log(sum).
// xor-butterfly gives bitwise-identical m,s on every lane (commutativity), so
// every lane's p matches the previously-passing trajectory exactly.
// ---------------------------------------------------------------------------
__global__ __launch_bounds__(256)
void lse_kernel(const float* __restrict__ unaries)
{
    const int row  = blockIdx.x * 8 + (threadIdx.x >> 5);
    const int lane = threadIdx.x & 31;
    float4 uv = ((const float4*)(unaries + (size_t)row * NN))[lane];
    float m = fmaxf(fmaxf(uv.x, uv.y), fmaxf(uv.z, uv.w));
    #pragma unroll
    for (int off = 16; off; off >>= 1)
        m = fmaxf(m, __shfl_xor_sync(FULLM, m, off));
    float s = fexp(uv.x - m) + fexp(uv.y - m) + fexp(uv.z - m) + fexp(uv.w - m);
    #pragma unroll
    for (int off = 16; off; off >>= 1)
        s += __shfl_xor_sync(FULLM, s, off);
    float ls = logf(s);
    float4 p4;
    p4.x = (uv.x - m) - ls;
    p4.y = (uv.y - m) - ls;
    p4.z = (uv.z - m) - ls;
    p4.w = (uv.w - m) - ls;
    ((float4*)(g_p + (size_t)row * NN))[lane] = p4;
}

// ---------------------------------------------------------------------------
// Kernel 2: forward, pure max. 512 threads, tid = cur*4 + g, 2 CTAs/SM (1 wave).
// 32 trans values/thread in regs (float2[16]); packed f32x2 adds; running-max
// accumulators (no register arrays); one float load (p) per step for g==0.
// Spill-free by construction (~59 regs).
// ---------------------------------------------------------------------------
__global__ __launch_bounds__(512, 2)
void viterbi_forward(const float* __restrict__ trans,
                     const void*  __restrict__ lengths)
{
    __shared__ float abuf[2][4 * GP];

    const int b   = blockIdx.x;
    const int tid = threadIdx.x;
    const int cur = tid >> 2;
    const int g   = tid & 3;          // prev in [g*32, g*32+32)
    const int L   = load_len(lengths, b);

    // loop-invariant transition scores: 32 floats = 16 packed pairs
    float2 tr[16];
    #pragma unroll
    for (int j = 0; j < 8; ++j) {
        float4 t4 = *(const float4*)(trans + cur * NN + g * 32 + j * 4);
        tr[2 * j]     = make_float2(t4.x, t4.y);
        tr[2 * j + 1] = make_float2(t4.z, t4.w);
    }

    const int wIdx = (cur >> 5) * GP + (cur & 31);
    if (g == 0) abuf[0][wIdx] = (cur == GO_IDX) ? 0.0f : NEGV;

    const float* prow = g_p     + (size_t)b * TT * NN + cur;
    float*       aout = g_alpha + (size_t)b * TT * NN + cur;
    float*       mout = g_mval  + (size_t)b * TT * NN + cur;

    float p = 0.f;
    if (g == 0) p = __ldg(prow);
    __syncthreads();

    for (int t = 0; t < L; ++t) {
        float pn = 0.f;
        if (g == 0) {
            int tn = (t + 1 < L) ? t + 1 : t;
            pn = __ldg(prow + (size_t)tn * NN);
        }
        const float* aS = abuf[t & 1] + g * GP;   // bank-disjoint per g

        float w0 = __int_as_float(0xff800000);
        float w1 = w0;
        #pragma unroll
        for (int j = 0; j < 8; ++j) {
            float4 a = *(const float4*)(aS + j * 4);
            float2 s0 = add2(make_float2(a.x, a.y), tr[2 * j]);
            float2 s1 = add2(make_float2(a.z, a.w), tr[2 * j + 1]);
            w0 = fmaxf(w0, fmaxf(s0.x, s0.y));
            w1 = fmaxf(w1, fmaxf(s1.x, s1.y));
        }
        float bv = fmaxf(w0, w1);
        bv = fmaxf(bv, __shfl_xor_sync(FULLM, bv, 1));
        bv = fmaxf(bv, __shfl_xor_sync(FULLM, bv, 2));

        if (g == 0) {
            float a = bv + p;                       // exact passing formula
            abuf[(t + 1) & 1][wIdx] = a;
            aout[(size_t)t * NN] = a;
            mout[(size_t)t * NN] = bv;
        }
        p = pn;
        __syncthreads();
    }

    // terminal argmax over prev (first-index), warp 0 only
    if (tid < 32) {
        const float* aF = abuf[L & 1];
        float bv = __int_as_float(0xff800000); int bi = 0;
        #pragma unroll
        for (int k = 0; k < 4; ++k) {
            int c = tid * 4 + k;
            float v = aF[(c >> 5) * GP + (c & 31)] + __ldg(trans + EOS_IDX * NN + c);
            if (v > bv) { bv = v; bi = c; }         // in-order: first-index ties
        }
        #pragma unroll
        for (int off = 16; off; off >>= 1) {
            float ov = __shfl_xor_sync(FULLM, bv, off);
            int   oi = __shfl_xor_sync(FULLM, bi, off);
            if (ov > bv || (ov == bv && oi < bi)) { bv = ov; bi = oi; }
        }
        if (tid == 0) { g_score[b] = bv; g_bestTag[b] = bi; }
    }
}

// ---------------------------------------------------------------------------
// Kernel 3: backtrace via equality against stored m (proven).
// ---------------------------------------------------------------------------
#define BT_SMEM (65536 + 8 * TT * 4)

__global__ __launch_bounds__(256)
void viterbi_backtrace(const float* __restrict__ trans,
                       const void*  __restrict__ lengths,
                       void* __restrict__ outv, int mode)
{
    extern __shared__ char smem[];
    float4* trS  = (float4*)smem;                 // [128][32] float4
    int*    path = (int*)(smem + 65536);          // [8][TT]

    const int tid = threadIdx.x;
    for (int i = tid; i < 128 * 32; i += 256)
        trS[i] = ((const float4*)trans)[i];
    __syncthreads();

    const int w    = tid >> 5;
    const int lane = tid & 31;
    const int b    = blockIdx.x * 8 + w;
    const int L    = load_len(lengths, b);
    int cur = g_bestTag[b];
    int* mypath = path + w * TT;
    if (lane == 0) mypath[L - 1] = cur;

    const float4* arow = (const float4*)(g_alpha + (size_t)b * TT * NN);
    const float4* mrow = (const float4*)(g_mval  + (size_t)b * TT * NN);

    const int t0 = L - 1;
    float4 ab0, ab1, mb0, mb1;
    ab0 = ab1 = mb0 = mb1 = make_float4(0.f, 0.f, 0.f, 0.f);
    if (t0 >= 1) { ab0 = arow[(size_t)(t0 - 1) * 32 + lane]; mb0 = mrow[(size_t)t0 * 32 + lane]; }
    if (t0 >= 2) { ab1 = arow[(size_t)(t0 - 2) * 32 + lane]; mb1 = mrow[(size_t)(t0 - 1) * 32 + lane]; }

    for (int t = t0; t >= 1; --t) {
        const int par = (t0 - t) & 1;
        float4 av = par ? ab1 : ab0;
        float4 mv = par ? mb1 : mb0;
        if (t >= 3) {
            float4 na = arow[(size_t)(t - 3) * 32 + lane];
            float4 nm = mrow[(size_t)(t - 2) * 32 + lane];
            if (par) { ab1 = na; mb1 = nm; } else { ab0 = na; mb0 = nm; }
        }
        const int sl   = cur >> 2;
        const int comp = cur & 3;
        float mc = (comp == 0) ? mv.x : (comp == 1) ? mv.y : (comp == 2) ? mv.z : mv.w;
        float mstar = __shfl_sync(FULLM, mc, sl);

        float4 tv = trS[cur * 32 + lane];
        float v0 = av.x + tv.x, v1 = av.y + tv.y;
        float v2 = av.z + tv.z, v3 = av.w + tv.w;
        bool e0 = (v0 == mstar), e1 = (v1 == mstar);
        bool e2 = (v2 == mstar), e3 = (v3 == mstar);
        unsigned mask = __ballot_sync(FULLM, e0 | e1 | e2 | e3);
        int wl = __ffs(mask) - 1;
        int lj = 3; if (e2) lj = 2; if (e1) lj = 1; if (e0) lj = 0;
        int ljw = __shfl_sync(FULLM, lj, wl);
        cur = wl * 4 + ljw;
        if (lane == 0) mypath[t - 1] = cur;
    }
    __syncwarp();

    float* outf = (float*)outv;
    int*   outi = (int*)outv;
    for (int tt = lane; tt < TT; tt += 32) {
        int v = (tt < L) ? mypath[tt] : 0;
        if (mode) outf[b * TT + tt] = (float)v;
        else      outi[b * TT + tt] = v;
    }
    if (mode && lane == 0) outf[BB * TT + b] = g_score[b];
}

extern "C" void kernel_launch(void* const* d_in, const int* in_sizes, int n_in,
                              void* d_out, int out_size)
{
    const float* unaries = (const float*)d_in[0];
    const float* trans   = (const float*)d_in[1];
    const void*  lengths = d_in[2];

    cudaFuncSetAttribute(viterbi_backtrace,
                         cudaFuncAttributeMaxDynamicSharedMemorySize, BT_SMEM);

    const int mode = (out_size == BB * TT + BB) ? 1 : 0;

    lse_kernel<<<(BB * TT) / 8, 256>>>(unaries);
    viterbi_forward<<<BB, 512>>>(trans, lengths);
    viterbi_backtrace<<<32, 256, BT_SMEM>>>(trans, lengths, d_out, mode);
}

// round 11
// speedup vs baseline: 1.4241x; 1.4153x over previous
#include <cuda_runtime.h>
#include <cstdint>
#include <cstddef>

#define BB 256
#define TT 512
#define NN 128
#define GO_IDX 1
#define EOS_IDX 2
#define NEGV -10000.0f
#define FULLM 0xffffffffu
#define GP 36   // padded stride (floats) per 32-float prev-group (144B, 16B-aligned)

__device__ float g_alpha[(size_t)BB * TT * NN];   // alpha_t rows
__device__ float g_mval [(size_t)BB * TT * NN];   // pre-unary max rows
__device__ float g_p    [(size_t)BB * TT * NN];   // precomputed log_softmax(unaries)
__device__ float g_score[BB];
__device__ int   g_bestTag[BB];

__device__ __forceinline__ int load_len(const void* lp, int b) {
    const int* p32 = (const int*)lp;
    if (p32[1] == 0) return (int)((const long long*)lp)[b];
    return p32[b];
}

// FFMA-pipe exp (~1e-9 rel on [-87,0])
__device__ __forceinline__ float fexp(float x) {
    float t  = fmaf(x, 1.4426950408889634f, 12582912.0f);
    int   ni = __float_as_int(t) - 0x4B400000;
    float n  = t - 12582912.0f;
    float r  = fmaf(n, -0.693359375f, x);
    r        = fmaf(n,  2.12194440e-4f, r);
    float p  = 1.9841270e-4f;
    p = fmaf(p, r, 1.3888889e-3f);
    p = fmaf(p, r, 8.3333333e-3f);
    p = fmaf(p, r, 4.1666667e-2f);
    p = fmaf(p, r, 1.6666667e-1f);
    p = fmaf(p, r, 0.5f);
    p = fmaf(p, r, 1.0f);
    p = fmaf(p, r, 1.0f);
    int e = ni + 127; if (e < 1) e = 1;
    return p * __int_as_float(e << 23);
}

// ---------------------------------------------------------------------------
// Kernel 1: per-(b,t) log-softmax, materialized: p = (u - m) - log(sum).
// xor-butterfly gives bitwise-identical m,s on every lane, so p matches the
// proven trajectory exactly (rel_err unchanged since R3).
// ---------------------------------------------------------------------------
__global__ __launch_bounds__(256)
void lse_kernel(const float* __restrict__ unaries)
{
    const int row  = blockIdx.x * 8 + (threadIdx.x >> 5);
    const int lane = threadIdx.x & 31;
    float4 uv = ((const float4*)(unaries + (size_t)row * NN))[lane];
    float m = fmaxf(fmaxf(uv.x, uv.y), fmaxf(uv.z, uv.w));
    #pragma unroll
    for (int off = 16; off; off >>= 1)
        m = fmaxf(m, __shfl_xor_sync(FULLM, m, off));
    float s = fexp(uv.x - m) + fexp(uv.y - m) + fexp(uv.z - m) + fexp(uv.w - m);
    #pragma unroll
    for (int off = 16; off; off >>= 1)
        s += __shfl_xor_sync(FULLM, s, off);
    float ls = logf(s);
    float4 p4;
    p4.x = (uv.x - m) - ls;
    p4.y = (uv.y - m) - ls;
    p4.z = (uv.z - m) - ls;
    p4.w = (uv.w - m) - ls;
    ((float4*)(g_p + (size_t)row * NN))[lane] = p4;
}

// ---------------------------------------------------------------------------
// Kernel 2: forward, pure max. 512 threads, tid = cur*4 + g, 2 CTAs/SM (1 wave).
// Scalar FADD/FMNMX, 4 running accumulators (no register arrays, no asm),
// trans in regs as float4[8] (32 regs). ~58 regs total: spill-free under the
// 64-reg cap. One barrier/step; p prefetched one step ahead.
// ---------------------------------------------------------------------------
__global__ __launch_bounds__(512, 2)
void viterbi_forward(const float* __restrict__ trans,
                     const void*  __restrict__ lengths)
{
    __shared__ float abuf[2][4 * GP];

    const int b   = blockIdx.x;
    const int tid = threadIdx.x;
    const int cur = tid >> 2;
    const int g   = tid & 3;          // prev in [g*32, g*32+32)
    const int L   = load_len(lengths, b);

    // loop-invariant transition scores: 32 floats, kept as 8 float4 (32 regs)
    float4 tr[8];
    #pragma unroll
    for (int j = 0; j < 8; ++j)
        tr[j] = *(const float4*)(trans + cur * NN + g * 32 + j * 4);

    const int wIdx = (cur >> 5) * GP + (cur & 31);
    if (g == 0) abuf[0][wIdx] = (cur == GO_IDX) ? 0.0f : NEGV;

    const float* prow = g_p     + (size_t)b * TT * NN + cur;
    float*       aout = g_alpha + (size_t)b * TT * NN + cur;
    float*       mout = g_mval  + (size_t)b * TT * NN + cur;

    float p = 0.f;
    if (g == 0) p = __ldg(prow);
    __syncthreads();

    const float NI = __int_as_float(0xff800000);

    for (int t = 0; t < L; ++t) {
        float pn = 0.f;
        if (g == 0) {
            int tn = (t + 1 < L) ? t + 1 : t;
            pn = __ldg(prow + (size_t)tn * NN);
        }
        const float* aS = abuf[t & 1] + g * GP;   // bank-disjoint per g

        float w0 = NI, w1 = NI, w2 = NI, w3 = NI;
        #pragma unroll
        for (int j = 0; j < 8; ++j) {
            float4 a = *(const float4*)(aS + j * 4);
            w0 = fmaxf(w0, a.x + tr[j].x);
            w1 = fmaxf(w1, a.y + tr[j].y);
            w2 = fmaxf(w2, a.z + tr[j].z);
            w3 = fmaxf(w3, a.w + tr[j].w);
        }
        float bv = fmaxf(fmaxf(w0, w1), fmaxf(w2, w3));
        bv = fmaxf(bv, __shfl_xor_sync(FULLM, bv, 1));
        bv = fmaxf(bv, __shfl_xor_sync(FULLM, bv, 2));

        if (g == 0) {
            float a = bv + p;                       // exact passing formula
            abuf[(t + 1) & 1][wIdx] = a;
            aout[(size_t)t * NN] = a;
            mout[(size_t)t * NN] = bv;
        }
        p = pn;
        __syncthreads();
    }

    // terminal argmax over prev (first-index), warp 0 only
    if (tid < 32) {
        const float* aF = abuf[L & 1];
        float bv = NI; int bi = 0;
        #pragma unroll
        for (int k = 0; k < 4; ++k) {
            int c = tid * 4 + k;
            float v = aF[(c >> 5) * GP + (c & 31)] + __ldg(trans + EOS_IDX * NN + c);
            if (v > bv) { bv = v; bi = c; }         // in-order: first-index ties
        }
        #pragma unroll
        for (int off = 16; off; off >>= 1) {
            float ov = __shfl_xor_sync(FULLM, bv, off);
            int   oi = __shfl_xor_sync(FULLM, bi, off);
            if (ov > bv || (ov == bv && oi < bi)) { bv = ov; bi = oi; }
        }
        if (tid == 0) { g_score[b] = bv; g_bestTag[b] = bi; }
    }
}

// ---------------------------------------------------------------------------
// Kernel 3: backtrace via equality against stored m (proven, ~40us).
// ---------------------------------------------------------------------------
#define BT_SMEM (65536 + 8 * TT * 4)

__global__ __launch_bounds__(256)
void viterbi_backtrace(const float* __restrict__ trans,
                       const void*  __restrict__ lengths,
                       void* __restrict__ outv, int mode)
{
    extern __shared__ char smem[];
    float4* trS  = (float4*)smem;                 // [128][32] float4
    int*    path = (int*)(smem + 65536);          // [8][TT]

    const int tid = threadIdx.x;
    for (int i = tid; i < 128 * 32; i += 256)
        trS[i] = ((const float4*)trans)[i];
    __syncthreads();

    const int w    = tid >> 5;
    const int lane = tid & 31;
    const int b    = blockIdx.x * 8 + w;
    const int L    = load_len(lengths, b);
    int cur = g_bestTag[b];
    int* mypath = path + w * TT;
    if (lane == 0) mypath[L - 1] = cur;

    const float4* arow = (const float4*)(g_alpha + (size_t)b * TT * NN);
    const float4* mrow = (const float4*)(g_mval  + (size_t)b * TT * NN);

    const int t0 = L - 1;
    float4 ab0, ab1, mb0, mb1;
    ab0 = ab1 = mb0 = mb1 = make_float4(0.f, 0.f, 0.f, 0.f);
    if (t0 >= 1) { ab0 = arow[(size_t)(t0 - 1) * 32 + lane]; mb0 = mrow[(size_t)t0 * 32 + lane]; }
    if (t0 >= 2) { ab1 = arow[(size_t)(t0 - 2) * 32 + lane]; mb1 = mrow[(size_t)(t0 - 1) * 32 + lane]; }

    for (int t = t0; t >= 1; --t) {
        const int par = (t0 - t) & 1;
        float4 av = par ? ab1 : ab0;
        float4 mv = par ? mb1 : mb0;
        if (t >= 3) {
            float4 na = arow[(size_t)(t - 3) * 32 + lane];
            float4 nm = mrow[(size_t)(t - 2) * 32 + lane];
            if (par) { ab1 = na; mb1 = nm; } else { ab0 = na; mb0 = nm; }
        }
        const int sl   = cur >> 2;
        const int comp = cur & 3;
        float mc = (comp == 0) ? mv.x : (comp == 1) ? mv.y : (comp == 2) ? mv.z : mv.w;
        float mstar = __shfl_sync(FULLM, mc, sl);

        float4 tv = trS[cur * 32 + lane];
        float v0 = av.x + tv.x, v1 = av.y + tv.y;
        float v2 = av.z + tv.z, v3 = av.w + tv.w;
        bool e0 = (v0 == mstar), e1 = (v1 == mstar);
        bool e2 = (v2 == mstar), e3 = (v3 == mstar);
        unsigned mask = __ballot_sync(FULLM, e0 | e1 | e2 | e3);
        int wl = __ffs(mask) - 1;
        int lj = 3; if (e2) lj = 2; if (e1) lj = 1; if (e0) lj = 0;
        int ljw = __shfl_sync(FULLM, lj, wl);
        cur = wl * 4 + ljw;
        if (lane == 0) mypath[t - 1] = cur;
    }
    __syncwarp();

    float* outf = (float*)outv;
    int*   outi = (int*)outv;
    for (int tt = lane; tt < TT; tt += 32) {
        int v = (tt < L) ? mypath[tt] : 0;
        if (mode) outf[b * TT + tt] = (float)v;
        else      outi[b * TT + tt] = v;
    }
    if (mode && lane == 0) outf[BB * TT + b] = g_score[b];
}

extern "C" void kernel_launch(void* const* d_in, const int* in_sizes, int n_in,
                              void* d_out, int out_size)
{
    const float* unaries = (const float*)d_in[0];
    const float* trans   = (const float*)d_in[1];
    const void*  lengths = d_in[2];

    cudaFuncSetAttribute(viterbi_backtrace,
                         cudaFuncAttributeMaxDynamicSharedMemorySize, BT_SMEM);

    const int mode = (out_size == BB * TT + BB) ? 1 : 0;

    lse_kernel<<<(BB * TT) / 8, 256>>>(unaries);
    viterbi_forward<<<BB, 512>>>(trans, lengths);
    viterbi_backtrace<<<32, 256, BT_SMEM>>>(trans, lengths, d_out, mode);
}